// round 15
// baseline (speedup 1.0000x reference)
#include <cuda_runtime.h>
#include <cuda_fp16.h>
#include <cuda_bf16.h>
#include <cstdint>

// ---------------- dims ----------------
#define B_  2
#define S_  1024
#define D_  1024
#define H_  16
#define DH_ 64
#define DFF_ 4096
#define L_  2
#define V_  32000
#define GS_ 128
#define NT_ (B_*S_)   // 2048 tokens

// weight regions in g_wh (element offsets, halves)
#define OFF_QKV 0ull                       // 2 layers x 3M
#define OFF_O   (6ull*1024*1024)           // 2 x 1M
#define OFF_GU  (8ull*1024*1024)           // 2 x 8M (interleaved gate/up)
#define OFF_DN  (24ull*1024*1024)          // 2 x 4M
#define OFF_HD  (32ull*1024*1024)          // 32.77M
#define WH_TOT  (66ull*1024*1024)

// ---------------- scratch ----------------
__device__ __align__(16) float  g_x  [NT_*D_];
__device__ __align__(16) __half g_qkv[NT_*3*D_];
__device__ __align__(16) __half g_hh [NT_*D_];
__device__ __align__(16) __half g_oh [NT_*D_];
__device__ __align__(16) __half g_gh [NT_*DFF_];
__device__ __align__(16) __half g_wh [WH_TOT];
__device__ float g_scqkv[2*3*8192];
__device__ float g_scgu [2*2*32768];       // interleaved gate/up scales
__device__ int   g_wfmt;   // 0=int8, 1=int32, 2=bf16

// ---------------- weight format detector ----------------
__global__ void detect_fmt_kernel(const void* __restrict__ w)
{
    const unsigned* u = (const unsigned*)w;
    bool i32 = true, b16 = true;
    for (int i = 0; i < 64; i++) {
        unsigned x = u[i];
        if (!(x == 0u || x == 1u || x == 0xFFFFFFFFu)) i32 = false;
        unsigned lo = x & 0xFFFFu, hi = x >> 16;
        bool lok = (lo == 0u || lo == 0x3F80u || lo == 0xBF80u);
        bool hok = (hi == 0u || hi == 0x3F80u || hi == 0xBF80u);
        if (!(lok && hok)) b16 = false;
    }
    g_wfmt = i32 ? 1 : (b16 ? 2 : 0);
}

__device__ __forceinline__ void load_w4(const void* W, size_t idx, int fmt,
                                        float& w0, float& w1, float& w2, float& w3)
{
    if (fmt == 1) {
        int4 wv = *(const int4*)((const int*)W + idx);
        w0 = (float)wv.x; w1 = (float)wv.y; w2 = (float)wv.z; w3 = (float)wv.w;
    } else if (fmt == 2) {
        uint2 v = *(const uint2*)((const __nv_bfloat16*)W + idx);
        w0 = __bfloat162float(__ushort_as_bfloat16((unsigned short)( v.x        & 0xFFFFu)));
        w1 = __bfloat162float(__ushort_as_bfloat16((unsigned short)( v.x >> 16          )));
        w2 = __bfloat162float(__ushort_as_bfloat16((unsigned short)( v.y        & 0xFFFFu)));
        w3 = __bfloat162float(__ushort_as_bfloat16((unsigned short)( v.y >> 16          )));
    } else {
        int wv = *(const int*)((const int8_t*)W + idx);
        w0 = (float)(int8_t)( wv         & 0xff);
        w1 = (float)(int8_t)((wv >> 8 )  & 0xff);
        w2 = (float)(int8_t)((wv >> 16)  & 0xff);
        w3 = (float)(int8_t)( wv >> 24         );
    }
}

// ---------------- fused weight conversion ----------------
#define NSEG 7
struct ConvSegs {
    const void*        src[NSEG];
    unsigned long long srcOff[NSEG];
    unsigned long long dstOff[NSEG];
    int                mode[NSEG];     // 0 plain, 1 interleave-even, 2 interleave-odd
    int                chunkEnd[NSEG];
    int                total;
};

__global__ void convert_all(ConvSegs P, __half* __restrict__ dst)
{
    const int fmt = g_wfmt;
    for (int chunk = blockIdx.x * blockDim.x + threadIdx.x; chunk < P.total;
         chunk += gridDim.x * blockDim.x) {
        int s = 0;
        while (chunk >= P.chunkEnd[s]) s++;
        int start = (s == 0) ? 0 : P.chunkEnd[s - 1];
        size_t i = (size_t)(chunk - start) * 16;

        float w[16];
#pragma unroll
        for (int j = 0; j < 4; j++)
            load_w4(P.src[s], P.srcOff[s] + i + j*4, fmt,
                    w[j*4], w[j*4+1], w[j*4+2], w[j*4+3]);
        uint32_t h[8];
#pragma unroll
        for (int j = 0; j < 8; j++) {
            __half2 p = __floats2half2_rn(w[2*j], w[2*j+1]);
            h[j] = *(uint32_t*)&p;
        }
        size_t di;
        int mode = P.mode[s];
        if (mode == 0) {
            di = (size_t)P.dstOff[s] + i;
        } else {
            size_t row = i >> 10, col = i & 1023;
            di = (size_t)P.dstOff[s] + ((2*row + (mode - 1)) << 10) + col;
        }
        *(uint4*)&dst[di]     = make_uint4(h[0], h[1], h[2], h[3]);
        *(uint4*)&dst[di + 8] = make_uint4(h[4], h[5], h[6], h[7]);
    }
}

// ---------------- scale packing ----------------
__global__ void pack_scales(const float* __restrict__ qs, const float* __restrict__ ks,
                            const float* __restrict__ vs, const float* __restrict__ gs,
                            const float* __restrict__ us,
                            float* __restrict__ scqkv, float* __restrict__ scgu)
{
    int i = blockIdx.x * 256 + threadIdx.x;
    if (i < 49152) {
        int l = i / 24576, r = i % 24576;
        int which = r / 8192, j = r % 8192;
        const float* sp = (which == 0) ? qs : ((which == 1) ? ks : vs);
        scqkv[i] = sp[l*8192 + j];
    } else if (i < 180224) {
        int k = i - 49152;
        int l = k / 65536, r = k % 65536;
        int which = r / 32768, j = r % 32768;
        int row = j >> 3, g = j & 7;
        scgu[l*65536 + ((2*row + which) << 3) + g] = (which ? us : gs)[l*32768 + j];
    }
}

// ---------------- embedding gather + dequant ----------------
__global__ void embed_kernel(const int* __restrict__ ids,
                             const void* __restrict__ et,
                             const float* __restrict__ es,
                             float* __restrict__ X)
{
    int token = blockIdx.x;
    int id = ids[token];
    int d0 = threadIdx.x * 4;
    int fmt = g_wfmt;
    float w0, w1, w2, w3;
    load_w4(et, (size_t)id * D_ + d0, fmt, w0, w1, w2, w3);
    float s = es[id * (D_/GS_) + (d0 >> 7)];
    *(float4*)(X + (size_t)token * D_ + d0) = make_float4(w0*s, w1*s, w2*s, w3*s);
}

// ---------------- rmsnorm (f32 in, f16 out) ----------------
__global__ void rmsnorm_kernel(const float* __restrict__ X,
                               const float* __restrict__ w,
                               __half* __restrict__ Y)
{
    int row = blockIdx.x;
    const float* x = X + (size_t)row * D_;
    float ss = 0.f;
    float vals[4];
#pragma unroll
    for (int j = 0; j < 4; j++) {
        vals[j] = x[threadIdx.x + j*256];
        ss += vals[j]*vals[j];
    }
    __shared__ float red[256];
    red[threadIdx.x] = ss;
    __syncthreads();
    for (int s = 128; s > 0; s >>= 1) {
        if (threadIdx.x < s) red[threadIdx.x] += red[threadIdx.x + s];
        __syncthreads();
    }
    float rs = rsqrtf(red[0] * (1.0f/(float)D_) + 1e-6f);
#pragma unroll
    for (int j = 0; j < 4; j++) {
        int d = threadIdx.x + j*256;
        Y[(size_t)row * D_ + d] = __float2half(vals[j] * rs * w[d]);
    }
}

// ---------------- mma helpers ----------------
__device__ __forceinline__ void mma16816(float* c, const uint32_t* a, const uint32_t* b)
{
    asm volatile(
        "mma.sync.aligned.m16n8k16.row.col.f32.f16.f16.f32 "
        "{%0,%1,%2,%3}, {%4,%5,%6,%7}, {%8,%9}, {%0,%1,%2,%3};\n"
        : "+f"(c[0]), "+f"(c[1]), "+f"(c[2]), "+f"(c[3])
        : "r"(a[0]), "r"(a[1]), "r"(a[2]), "r"(a[3]), "r"(b[0]), "r"(b[1]));
}
__device__ __forceinline__ void cp16(uint32_t dst, const void* src)
{
    asm volatile("cp.async.cg.shared.global [%0], [%1], 16;\n" :: "r"(dst), "l"(src));
}
__device__ __forceinline__ void ldm_x4(uint32_t& r0, uint32_t& r1, uint32_t& r2, uint32_t& r3,
                                       uint32_t addr)
{
    asm volatile("ldmatrix.sync.aligned.m8n8.x4.shared.b16 {%0,%1,%2,%3}, [%4];"
                 : "=r"(r0), "=r"(r1), "=r"(r2), "=r"(r3) : "r"(addr));
}
__device__ __forceinline__ uint32_t smem_u32(const void* p) {
    return (uint32_t)__cvta_generic_to_shared(p);
}

// ---------------- async HMMA GEMM (4 warps, 64-wide warp tiles) ----------------
// OP=0: f32 store.  OP=1: f32 accumulate.  OP=2: f16 store.
// OP=3: fused silu(gate)*up -> f16 [M, N/2] (weights interleaved gate/up).
#define BN 128
#define BKT 32
#define BSTG (BN*BKT*2)

template<int OP, int MT>
__global__ void __launch_bounds__(128, 2)
gemm_async(const __half* __restrict__ A, const __half* __restrict__ Wh,
           const float* __restrict__ Sc, void* __restrict__ Cv,
           int M, int N, int K)
{
    constexpr int BM   = MT * 32;
    constexpr int ASTG = BM * BKT * 2;
    __shared__ __align__(16) __half As[3][BM*BKT];
    __shared__ __align__(16) __half Bs[3][BN*BKT];

    const int tid  = threadIdx.x;
    const int lane = tid & 31;
    const int wid  = tid >> 5;            // 0..3
    const int warp_m = wid >> 1;          // 0..1
    const int warp_n = wid & 1;           // 0..1 (64 cols each)
    const int m0 = blockIdx.x * BM;
    const int n0 = blockIdx.y * BN;
    const int ngroups = K >> 7;
    const int gid = lane >> 2, tig = lane & 3;

    const uint32_t sa = smem_u32(&As[0][0]);
    const uint32_t sb = smem_u32(&Bs[0][0]);

    const int a_row  = lane & 15;
    const int a_sel  = lane >> 4;
    const int a_xor  = ((lane & 15) >> 1) & 3;
    const int b_roff = ((lane >> 4) << 3) + (lane & 7);
    const int b_sel  = (lane >> 3) & 1;
    const int b_xor  = (b_roff >> 1) & 3;

    float acc[MT][8][4] = {};
    float s_cur[8][2];
    float s_nxt[8][2];

    const int iters = K / BKT;

    auto issue = [&](int stage, int k0) {
        uint32_t ab = sa + stage * ASTG;
        uint32_t bb = sb + stage * BSTG;
#pragma unroll
        for (int j = 0; j < MT; j++) {
            int c = tid + j*128;
            int row = c >> 2, ch = c & 3;
            int pch = ch ^ ((row >> 1) & 3);
            cp16(ab + row*64 + pch*16, A  + (size_t)(m0+row)*K + k0 + ch*8);
        }
#pragma unroll
        for (int j = 0; j < 4; j++) {
            int c = tid + j*128;
            int row = c >> 2, ch = c & 3;
            int pch = ch ^ ((row >> 1) & 3);
            cp16(bb + row*64 + pch*16, Wh + (size_t)(n0+row)*K + k0 + ch*8);
        }
        asm volatile("cp.async.commit_group;\n");
    };

    issue(0, 0);
    issue(1, BKT);

    int stage = 0;
    for (int it = 0; it < iters; it++) {
        if (it + 1 < iters) asm volatile("cp.async.wait_group 1;\n");
        else                asm volatile("cp.async.wait_group 0;\n");
        __syncthreads();

        if ((it & 3) == 0) {
            int g = it >> 2;
#pragma unroll
            for (int nt = 0; nt < 8; nt++) {
                int nc = warp_n*64 + nt*8 + 2*tig;
                float ns0, ns1;
                if (g == 0) {
                    ns0 = Sc[(size_t)(n0 + nc)    *ngroups];
                    ns1 = Sc[(size_t)(n0 + nc + 1)*ngroups];
                } else {
                    ns0 = s_nxt[nt][0]; ns1 = s_nxt[nt][1];
                }
                if (it) {
                    float r0 = __fdividef(s_cur[nt][0], ns0);
                    float r1 = __fdividef(s_cur[nt][1], ns1);
#pragma unroll
                    for (int mt = 0; mt < MT; mt++) {
                        acc[mt][nt][0] *= r0; acc[mt][nt][1] *= r1;
                        acc[mt][nt][2] *= r0; acc[mt][nt][3] *= r1;
                    }
                }
                s_cur[nt][0] = ns0; s_cur[nt][1] = ns1;
            }
            if (g + 1 < ngroups) {
#pragma unroll
                for (int nt = 0; nt < 8; nt++) {
                    int nc = warp_n*64 + nt*8 + 2*tig;
                    s_nxt[nt][0] = Sc[(size_t)(n0 + nc)    *ngroups + g + 1];
                    s_nxt[nt][1] = Sc[(size_t)(n0 + nc + 1)*ngroups + g + 1];
                }
            }
        }

        const uint32_t ab = sa + stage * ASTG;
        const uint32_t bb = sb + stage * BSTG;
#pragma unroll
        for (int kk = 0; kk < 2; kk++) {
            uint32_t af[MT][4];
#pragma unroll
            for (int mt = 0; mt < MT; mt++) {
                int row = warp_m*(16*MT) + mt*16 + a_row;
                int pch = (kk*2 + a_sel) ^ a_xor;
                ldm_x4(af[mt][0], af[mt][1], af[mt][2], af[mt][3],
                       ab + row*64 + pch*16);
            }
            uint32_t bf[8][2];
#pragma unroll
            for (int p = 0; p < 4; p++) {
                int row = warp_n*64 + p*16 + b_roff;
                int pch = (kk*2 + b_sel) ^ b_xor;
                uint32_t r0, r1, r2, r3;
                ldm_x4(r0, r1, r2, r3, bb + row*64 + pch*16);
                bf[2*p  ][0] = r0; bf[2*p  ][1] = r1;
                bf[2*p+1][0] = r2; bf[2*p+1][1] = r3;
            }
#pragma unroll
            for (int mt = 0; mt < MT; mt++)
#pragma unroll
                for (int nt = 0; nt < 8; nt++)
                    mma16816(acc[mt][nt], af[mt], bf[nt]);
        }

        if (it + 2 < iters) issue((stage + 2 >= 3) ? stage - 1 : stage + 2, (it + 2) * BKT);
        stage = (stage + 1 == 3) ? 0 : stage + 1;
    }

    // ---- epilogue ----
#pragma unroll
    for (int mt = 0; mt < MT; mt++) {
        int r = m0 + warp_m*(16*MT) + mt*16 + gid;
#pragma unroll
        for (int nt = 0; nt < 8; nt++) {
            int c = n0 + warp_n*64 + nt*8 + 2*tig;
            float s0 = s_cur[nt][0], s1 = s_cur[nt][1];
            float v00 = acc[mt][nt][0]*s0, v01 = acc[mt][nt][1]*s1;
            float v10 = acc[mt][nt][2]*s0, v11 = acc[mt][nt][3]*s1;
            if (OP == 0 || OP == 1) {
                float* C = (float*)Cv;
                float* p0 = C + (size_t)r*N + c;
                float* p1 = C + (size_t)(r+8)*N + c;
                float2 v0 = make_float2(v00, v01);
                float2 v1 = make_float2(v10, v11);
                if (OP == 1) {
                    float2 o0 = *(float2*)p0, o1 = *(float2*)p1;
                    v0.x += o0.x; v0.y += o0.y; v1.x += o1.x; v1.y += o1.y;
                }
                *(float2*)p0 = v0;
                *(float2*)p1 = v1;
            } else if (OP == 2) {
                __half* C = (__half*)Cv;
                *(__half2*)(C + (size_t)r*N + c)     = __floats2half2_rn(v00, v01);
                *(__half2*)(C + (size_t)(r+8)*N + c) = __floats2half2_rn(v10, v11);
            } else {
                __half* C = (__half*)Cv;
                int oN = N >> 1, oc = c >> 1;
                float o0 = v00 / (1.f + __expf(-v00)) * v01;
                float o1 = v10 / (1.f + __expf(-v10)) * v11;
                C[(size_t)r*oN + oc]     = __float2half(o0);
                C[(size_t)(r+8)*oN + oc] = __float2half(o1);
            }
        }
    }
}

// ---------------- mma flash attention + per-head residual ----------------
// Vt uses a XOR-swizzled [64][64] layout: chunk' = chunk ^ (row&7) ^ ((row>>3)&7)
#define AQ 64
#define QKVS (3*D_)
__global__ void __launch_bounds__(128)
attn_mma(const __half* __restrict__ QKV, const __half* __restrict__ Hn,
         const float* __restrict__ alpha, __half* __restrict__ O, int layer)
{
    __shared__ __align__(16) __half Qs[AQ][72];
    __shared__ __align__(16) __half Ks[AQ][72];
    __shared__ __align__(16) __half Vt[AQ][64];   // swizzled [dh][key]

    const int tid = threadIdx.x, lane = tid & 31, wid = tid >> 5;
    const int qt = blockIdx.x, hh = blockIdx.y, b = blockIdx.z;
    const int q0 = qt * AQ;

    for (int t = tid; t < AQ*8; t += 128) {
        int r = t >> 3, c8 = t & 7;
        *(uint4*)&Qs[r][c8*8] =
            *(const uint4*)(QKV + ((size_t)(b*S_ + q0 + r))*QKVS + hh*DH_ + c8*8);
    }
    __syncthreads();

    uint32_t qf[4][4];
    {
        int rr = wid*16 + (lane & 15);
        int cc = ((lane >> 4) & 1) * 8;
#pragma unroll
        for (int ks = 0; ks < 4; ks++)
            ldm_x4(qf[ks][0], qf[ks][1], qf[ks][2], qf[ks][3],
                   smem_u32(&Qs[rr][ks*16 + cc]));
    }

    float o[8][4] = {};
    float m_lo = -1e30f, m_hi = -1e30f, l_lo = 0.f, l_hi = 0.f;
    const int qi_lo = q0 + wid*16 + (lane >> 2);
    const int qi_hi = qi_lo + 8;
    const int row_off = ((lane >> 4) << 3) + (lane & 7);
    const int col_sel = ((lane >> 3) & 1) * 8;

    for (int t0 = 0; t0 < q0 + AQ; t0 += AQ) {
        __syncthreads();
        for (int t = tid; t < AQ*8; t += 128) {
            int r = t >> 3, c8 = t & 7;
            const __half* base = QKV + ((size_t)(b*S_ + t0 + r))*QKVS + hh*DH_ + c8*8;
            *(uint4*)&Ks[r][c8*8] = *(const uint4*)(base + D_);
            uint4 raw = *(const uint4*)(base + 2*D_);
            const __half* hp = (const __half*)&raw;
            int rc = r >> 3, rw = r & 7;
#pragma unroll
            for (int d = 0; d < 8; d++) {
                // Vt row = c8*8+d; (row>>3)&7 = c8, row&7 = d
                int sc = rc ^ d ^ c8;
                Vt[c8*8 + d][sc*8 + rw] = hp[d];
            }
        }
        __syncthreads();

        float sacc[8][4] = {};
#pragma unroll
        for (int ks = 0; ks < 4; ks++) {
#pragma unroll
            for (int jp = 0; jp < 4; jp++) {
                uint32_t r0, r1, r2, r3;
                ldm_x4(r0, r1, r2, r3, smem_u32(&Ks[jp*16 + row_off][ks*16 + col_sel]));
                uint32_t bA[2] = {r0, r1};
                uint32_t bB[2] = {r2, r3};
                mma16816(sacc[2*jp  ], qf[ks], bA);
                mma16816(sacc[2*jp+1], qf[ks], bB);
            }
        }

        float mx_lo = -1e30f, mx_hi = -1e30f;
#pragma unroll
        for (int j = 0; j < 8; j++) {
            int kb = t0 + j*8 + 2*(lane & 3);
            sacc[j][0] = (kb     <= qi_lo) ? sacc[j][0]*0.125f : -1e30f;
            sacc[j][1] = (kb + 1 <= qi_lo) ? sacc[j][1]*0.125f : -1e30f;
            sacc[j][2] = (kb     <= qi_hi) ? sacc[j][2]*0.125f : -1e30f;
            sacc[j][3] = (kb + 1 <= qi_hi) ? sacc[j][3]*0.125f : -1e30f;
            mx_lo = fmaxf(mx_lo, fmaxf(sacc[j][0], sacc[j][1]));
            mx_hi = fmaxf(mx_hi, fmaxf(sacc[j][2], sacc[j][3]));
        }
        mx_lo = fmaxf(mx_lo, __shfl_xor_sync(0xffffffffu, mx_lo, 1));
        mx_lo = fmaxf(mx_lo, __shfl_xor_sync(0xffffffffu, mx_lo, 2));
        mx_hi = fmaxf(mx_hi, __shfl_xor_sync(0xffffffffu, mx_hi, 1));
        mx_hi = fmaxf(mx_hi, __shfl_xor_sync(0xffffffffu, mx_hi, 2));

        float mn_lo = fmaxf(m_lo, mx_lo), mn_hi = fmaxf(m_hi, mx_hi);
        float c_lo = __expf(m_lo - mn_lo), c_hi = __expf(m_hi - mn_hi);
        m_lo = mn_lo; m_hi = mn_hi;
        l_lo *= c_lo; l_hi *= c_hi;
#pragma unroll
        for (int j = 0; j < 8; j++) {
            o[j][0] *= c_lo; o[j][1] *= c_lo;
            o[j][2] *= c_hi; o[j][3] *= c_hi;
        }

        uint32_t pa[8], pb[8];
        float ps_lo = 0.f, ps_hi = 0.f;
#pragma unroll
        for (int j = 0; j < 8; j++) {
            float e0 = __expf(sacc[j][0] - mn_lo);
            float e1 = __expf(sacc[j][1] - mn_lo);
            float e2 = __expf(sacc[j][2] - mn_hi);
            float e3 = __expf(sacc[j][3] - mn_hi);
            ps_lo += e0 + e1; ps_hi += e2 + e3;
            __half2 hl = __floats2half2_rn(e0, e1);
            __half2 hb = __floats2half2_rn(e2, e3);
            pa[j] = *(uint32_t*)&hl;
            pb[j] = *(uint32_t*)&hb;
        }
        ps_lo += __shfl_xor_sync(0xffffffffu, ps_lo, 1);
        ps_lo += __shfl_xor_sync(0xffffffffu, ps_lo, 2);
        ps_hi += __shfl_xor_sync(0xffffffffu, ps_hi, 1);
        ps_hi += __shfl_xor_sync(0xffffffffu, ps_hi, 2);
        l_lo += ps_lo; l_hi += ps_hi;

#pragma unroll
        for (int kk = 0; kk < 4; kk++) {
            uint32_t af[4] = {pa[2*kk], pb[2*kk], pa[2*kk+1], pb[2*kk+1]};
#pragma unroll
            for (int dp = 0; dp < 4; dp++) {
                int row = dp*16 + row_off;
                int chunk = kk*2 + (col_sel >> 3);
                int sc = chunk ^ (row & 7) ^ ((row >> 3) & 7);
                uint32_t r0, r1, r2, r3;
                ldm_x4(r0, r1, r2, r3, smem_u32(&Vt[row][sc*8]));
                uint32_t bA[2] = {r0, r1};
                uint32_t bB[2] = {r2, r3};
                mma16816(o[2*dp  ], af, bA);
                mma16816(o[2*dp+1], af, bB);
            }
        }
    }

    float i_lo = 1.f / l_lo, i_hi = 1.f / l_hi;
    float a = alpha[layer*H_ + hh];
    size_t tok_lo = (size_t)(b*S_ + qi_lo);
#pragma unroll
    for (int j = 0; j < 8; j++) {
        int col = hh*DH_ + j*8 + 2*(lane & 3);
        float2 fh_lo = __half22float2(*(const __half2*)(Hn + tok_lo*D_ + col));
        float2 fh_hi = __half22float2(*(const __half2*)(Hn + (tok_lo+8)*D_ + col));
        __half2 o_lo = __floats2half2_rn(o[j][0]*i_lo + a*fh_lo.x,
                                         o[j][1]*i_lo + a*fh_lo.y);
        __half2 o_hi = __floats2half2_rn(o[j][2]*i_hi + a*fh_hi.x,
                                         o[j][3]*i_hi + a*fh_hi.y);
        *(__half2*)(O + tok_lo*D_ + col)     = o_lo;
        *(__half2*)(O + (tok_lo+8)*D_ + col) = o_hi;
    }
}

// ---------------- launch ----------------
extern "C" void kernel_launch(void* const* d_in, const int* in_sizes, int n_in,
                              void* d_out, int out_size)
{
    const int*   ids    = (const int*)  d_in[0];
    const void*  emb_t  = d_in[1];
    const float* emb_s  = (const float*)d_in[2];
    const void*  qt_    = d_in[3];
    const float* qs_    = (const float*)d_in[4];
    const void*  kt_    = d_in[5];
    const float* ks_    = (const float*)d_in[6];
    const void*  vt_    = d_in[7];
    const float* vs_    = (const float*)d_in[8];
    const void*  ot_    = d_in[9];
    const float* os_    = (const float*)d_in[10];
    const void*  gatet  = d_in[11];
    const float* gates  = (const float*)d_in[12];
    const void*  upt    = d_in[13];
    const float* ups    = (const float*)d_in[14];
    const void*  downt  = d_in[15];
    const float* downs  = (const float*)d_in[16];
    const float* wa     = (const float*)d_in[17];
    const float* wm     = (const float*)d_in[18];
    const float* alpha  = (const float*)d_in[19];
    const float* wf     = (const float*)d_in[20];
    const void*  headt  = d_in[21];
    const float* heads  = (const float*)d_in[22];
    float* out = (float*)d_out;

    float *x, *scqkv, *scgu;
    __half *qkv, *hh, *oh, *gh, *wh;
    cudaGetSymbolAddress((void**)&x,    g_x);
    cudaGetSymbolAddress((void**)&qkv,  g_qkv);
    cudaGetSymbolAddress((void**)&hh,   g_hh);
    cudaGetSymbolAddress((void**)&oh,   g_oh);
    cudaGetSymbolAddress((void**)&gh,   g_gh);
    cudaGetSymbolAddress((void**)&wh,   g_wh);
    cudaGetSymbolAddress((void**)&scqkv,g_scqkv);
    cudaGetSymbolAddress((void**)&scgu, g_scgu);

    static cudaStream_t s2 = nullptr;
    static cudaEvent_t evFork = nullptr, evA[2] = {nullptr, nullptr},
                       evB0 = nullptr, evH = nullptr;
    if (!s2) {
        cudaStreamCreate(&s2);
        cudaEventCreateWithFlags(&evFork, cudaEventDisableTiming);
        cudaEventCreateWithFlags(&evA[0], cudaEventDisableTiming);
        cudaEventCreateWithFlags(&evA[1], cudaEventDisableTiming);
        cudaEventCreateWithFlags(&evB0,   cudaEventDisableTiming);
        cudaEventCreateWithFlags(&evH,    cudaEventDisableTiming);
    }

    const size_t wDD = (size_t)D_*D_;          // 1M
    const size_t wFD = (size_t)DFF_*D_;        // 4M
    const size_t sDD = wDD/GS_;                // 8192
    const size_t sFD = wFD/GS_;                // 32768

    detect_fmt_kernel<<<1, 1>>>(emb_t);
    cudaEventRecord(evFork, 0);
    cudaStreamWaitEvent(s2, evFork, 0);

    auto launch_conv = [&](ConvSegs& P) {
        convert_all<<<(P.total + 255)/256, 256, 0, s2>>>(P, wh);
    };
    auto seg_init = [](ConvSegs& P) { P.total = 0; };
    auto seg_add = [](ConvSegs& P, int& seg, const void* src, size_t soff,
                      size_t doff, int nelems, int mode) {
        P.src[seg] = src; P.srcOff[seg] = soff; P.dstOff[seg] = doff;
        P.mode[seg] = mode; P.total += nelems / 16; P.chunkEnd[seg] = P.total; seg++;
    };

    // s2: L0 qkv+o -> evA0 ; L0 gu+dn -> evB0 ; L1 all -> evA1 ; head -> evH
    {
        ConvSegs P; seg_init(P); int seg = 0;
        seg_add(P, seg, qt_, 0, OFF_QKV,         (int)wDD, 0);
        seg_add(P, seg, kt_, 0, OFF_QKV + wDD,   (int)wDD, 0);
        seg_add(P, seg, vt_, 0, OFF_QKV + 2*wDD, (int)wDD, 0);
        seg_add(P, seg, ot_, 0, OFF_O,           (int)wDD, 0);
        launch_conv(P); cudaEventRecord(evA[0], s2);
    }
    {
        ConvSegs P; seg_init(P); int seg = 0;
        seg_add(P, seg, gatet, 0, OFF_GU, (int)wFD, 1);
        seg_add(P, seg, upt,   0, OFF_GU, (int)wFD, 2);
        seg_add(P, seg, downt, 0, OFF_DN, (int)wFD, 0);
        launch_conv(P); cudaEventRecord(evB0, s2);
    }
    {
        ConvSegs P; seg_init(P); int seg = 0;
        seg_add(P, seg, qt_,   wDD, OFF_QKV + 3*wDD,         (int)wDD, 0);
        seg_add(P, seg, kt_,   wDD, OFF_QKV + 3*wDD + wDD,   (int)wDD, 0);
        seg_add(P, seg, vt_,   wDD, OFF_QKV + 3*wDD + 2*wDD, (int)wDD, 0);
        seg_add(P, seg, ot_,   wDD, OFF_O  + wDD,            (int)wDD, 0);
        seg_add(P, seg, gatet, wFD, OFF_GU + 2*wFD,          (int)wFD, 1);
        seg_add(P, seg, upt,   wFD, OFF_GU + 2*wFD,          (int)wFD, 2);
        seg_add(P, seg, downt, wFD, OFF_DN + wFD,            (int)wFD, 0);
        launch_conv(P); cudaEventRecord(evA[1], s2);
    }
    {
        ConvSegs P; seg_init(P); int seg = 0;
        seg_add(P, seg, headt, 0, OFF_HD, V_*D_, 0);
        launch_conv(P); cudaEventRecord(evH, s2);
    }

    pack_scales<<<(180224 + 255)/256, 256>>>(qs_, ks_, vs_, gates, ups, scqkv, scgu);
    embed_kernel<<<NT_, 256>>>(ids, emb_t, emb_s, x);

    dim3 g_qkvp(NT_/128, 3*D_/BN);   // 16 x 24
    dim3 g_op  (NT_/64,  D_/BN);     // 32 x 8  (BM=64)
    dim3 g_gup (NT_/128, 2*DFF_/BN); // 16 x 64
    dim3 g_hd  (NT_/128, V_/BN);     // 16 x 250

    for (int l = 0; l < L_; l++) {
        rmsnorm_kernel<<<NT_, 256>>>(x, wa + (size_t)l*D_, hh);
        cudaStreamWaitEvent(0, evA[l], 0);
        gemm_async<2,4><<<g_qkvp, 128>>>(hh, wh + OFF_QKV + l*3*wDD, scqkv + l*3*sDD,
                                         qkv, NT_, 3*D_, D_);
        attn_mma<<<dim3(S_/AQ, H_, B_), 128>>>(qkv, hh, alpha, oh, l);
        gemm_async<1,2><<<g_op, 128>>>(oh, wh + OFF_O + l*wDD, os_ + l*sDD,
                                       x, NT_, D_, D_);

        rmsnorm_kernel<<<NT_, 256>>>(x, wm + (size_t)l*D_, hh);
        if (l == 0) cudaStreamWaitEvent(0, evB0, 0);
        gemm_async<3,4><<<g_gup, 128>>>(hh, wh + OFF_GU + l*2*wFD, scgu + l*2*sFD,
                                        gh, NT_, 2*DFF_, D_);
        gemm_async<1,2><<<g_op, 128>>>(gh, wh + OFF_DN + l*wFD, downs + l*sFD,
                                       x, NT_, D_, DFF_);
    }
    rmsnorm_kernel<<<NT_, 256>>>(x, wf, hh);

    cudaStreamWaitEvent(0, evH, 0);
    gemm_async<0,4><<<g_hd, 128>>>(hh, wh + OFF_HD, heads, out, NT_, V_, D_);
}

// round 16
// speedup vs baseline: 1.4649x; 1.4649x over previous
#include <cuda_runtime.h>
#include <cuda_fp16.h>
#include <cuda_bf16.h>
#include <cstdint>

// ---------------- dims ----------------
#define B_  2
#define S_  1024
#define D_  1024
#define H_  16
#define DH_ 64
#define DFF_ 4096
#define L_  2
#define V_  32000
#define GS_ 128
#define NT_ (B_*S_)   // 2048 tokens

// weight regions in g_wh (element offsets, halves)
#define OFF_QKV 0ull                       // 2 layers x 3M
#define OFF_O   (6ull*1024*1024)           // 2 x 1M
#define OFF_GU  (8ull*1024*1024)           // 2 x 8M (interleaved gate/up)
#define OFF_DN  (24ull*1024*1024)          // 2 x 4M
#define OFF_HD  (32ull*1024*1024)          // 32.77M
#define WH_TOT  (66ull*1024*1024)

// ---------------- scratch ----------------
__device__ __align__(16) float  g_x  [NT_*D_];
__device__ __align__(16) __half g_qkv[NT_*3*D_];
__device__ __align__(16) __half g_hh [NT_*D_];
__device__ __align__(16) __half g_oh [NT_*D_];
__device__ __align__(16) __half g_gh [NT_*DFF_];
__device__ __align__(16) __half g_wh [WH_TOT];
__device__ float g_scqkv[2*3*8192];
__device__ float g_scgu [2*2*32768];       // interleaved gate/up scales
__device__ int   g_wfmt;   // 0=int8, 1=int32, 2=bf16

// ---------------- weight format detector ----------------
__global__ void detect_fmt_kernel(const void* __restrict__ w)
{
    const unsigned* u = (const unsigned*)w;
    bool i32 = true, b16 = true;
    for (int i = 0; i < 64; i++) {
        unsigned x = u[i];
        if (!(x == 0u || x == 1u || x == 0xFFFFFFFFu)) i32 = false;
        unsigned lo = x & 0xFFFFu, hi = x >> 16;
        bool lok = (lo == 0u || lo == 0x3F80u || lo == 0xBF80u);
        bool hok = (hi == 0u || hi == 0x3F80u || hi == 0xBF80u);
        if (!(lok && hok)) b16 = false;
    }
    g_wfmt = i32 ? 1 : (b16 ? 2 : 0);
}

__device__ __forceinline__ void load_w4(const void* W, size_t idx, int fmt,
                                        float& w0, float& w1, float& w2, float& w3)
{
    if (fmt == 1) {
        int4 wv = *(const int4*)((const int*)W + idx);
        w0 = (float)wv.x; w1 = (float)wv.y; w2 = (float)wv.z; w3 = (float)wv.w;
    } else if (fmt == 2) {
        uint2 v = *(const uint2*)((const __nv_bfloat16*)W + idx);
        w0 = __bfloat162float(__ushort_as_bfloat16((unsigned short)( v.x        & 0xFFFFu)));
        w1 = __bfloat162float(__ushort_as_bfloat16((unsigned short)( v.x >> 16          )));
        w2 = __bfloat162float(__ushort_as_bfloat16((unsigned short)( v.y        & 0xFFFFu)));
        w3 = __bfloat162float(__ushort_as_bfloat16((unsigned short)( v.y >> 16          )));
    } else {
        int wv = *(const int*)((const int8_t*)W + idx);
        w0 = (float)(int8_t)( wv         & 0xff);
        w1 = (float)(int8_t)((wv >> 8 )  & 0xff);
        w2 = (float)(int8_t)((wv >> 16)  & 0xff);
        w3 = (float)(int8_t)( wv >> 24         );
    }
}

// ---------------- fused weight conversion ----------------
#define NSEG 7
struct ConvSegs {
    const void*        src[NSEG];
    unsigned long long srcOff[NSEG];
    unsigned long long dstOff[NSEG];
    int                mode[NSEG];     // 0 plain, 1 interleave-even, 2 interleave-odd
    int                chunkEnd[NSEG];
    int                total;
};

__global__ void convert_all(ConvSegs P, __half* __restrict__ dst)
{
    const int fmt = g_wfmt;
    for (int chunk = blockIdx.x * blockDim.x + threadIdx.x; chunk < P.total;
         chunk += gridDim.x * blockDim.x) {
        int s = 0;
        while (chunk >= P.chunkEnd[s]) s++;
        int start = (s == 0) ? 0 : P.chunkEnd[s - 1];
        size_t i = (size_t)(chunk - start) * 16;

        float w[16];
#pragma unroll
        for (int j = 0; j < 4; j++)
            load_w4(P.src[s], P.srcOff[s] + i + j*4, fmt,
                    w[j*4], w[j*4+1], w[j*4+2], w[j*4+3]);
        uint32_t h[8];
#pragma unroll
        for (int j = 0; j < 8; j++) {
            __half2 p = __floats2half2_rn(w[2*j], w[2*j+1]);
            h[j] = *(uint32_t*)&p;
        }
        size_t di;
        int mode = P.mode[s];
        if (mode == 0) {
            di = (size_t)P.dstOff[s] + i;
        } else {
            size_t row = i >> 10, col = i & 1023;
            di = (size_t)P.dstOff[s] + ((2*row + (mode - 1)) << 10) + col;
        }
        *(uint4*)&dst[di]     = make_uint4(h[0], h[1], h[2], h[3]);
        *(uint4*)&dst[di + 8] = make_uint4(h[4], h[5], h[6], h[7]);
    }
}

// ---------------- scale packing ----------------
__global__ void pack_scales(const float* __restrict__ qs, const float* __restrict__ ks,
                            const float* __restrict__ vs, const float* __restrict__ gs,
                            const float* __restrict__ us,
                            float* __restrict__ scqkv, float* __restrict__ scgu)
{
    int i = blockIdx.x * 256 + threadIdx.x;
    if (i < 49152) {
        int l = i / 24576, r = i % 24576;
        int which = r / 8192, j = r % 8192;
        const float* sp = (which == 0) ? qs : ((which == 1) ? ks : vs);
        scqkv[i] = sp[l*8192 + j];
    } else if (i < 180224) {
        int k = i - 49152;
        int l = k / 65536, r = k % 65536;
        int which = r / 32768, j = r % 32768;
        int row = j >> 3, g = j & 7;
        scgu[l*65536 + ((2*row + which) << 3) + g] = (which ? us : gs)[l*32768 + j];
    }
}

// ---------------- embedding gather + dequant ----------------
__global__ void embed_kernel(const int* __restrict__ ids,
                             const void* __restrict__ et,
                             const float* __restrict__ es,
                             float* __restrict__ X)
{
    int token = blockIdx.x;
    int id = ids[token];
    int d0 = threadIdx.x * 4;
    int fmt = g_wfmt;
    float w0, w1, w2, w3;
    load_w4(et, (size_t)id * D_ + d0, fmt, w0, w1, w2, w3);
    float s = es[id * (D_/GS_) + (d0 >> 7)];
    *(float4*)(X + (size_t)token * D_ + d0) = make_float4(w0*s, w1*s, w2*s, w3*s);
}

// ---------------- rmsnorm (f32 in, f16 out) ----------------
__global__ void rmsnorm_kernel(const float* __restrict__ X,
                               const float* __restrict__ w,
                               __half* __restrict__ Y)
{
    int row = blockIdx.x;
    const float* x = X + (size_t)row * D_;
    float ss = 0.f;
    float vals[4];
#pragma unroll
    for (int j = 0; j < 4; j++) {
        vals[j] = x[threadIdx.x + j*256];
        ss += vals[j]*vals[j];
    }
    __shared__ float red[256];
    red[threadIdx.x] = ss;
    __syncthreads();
    for (int s = 128; s > 0; s >>= 1) {
        if (threadIdx.x < s) red[threadIdx.x] += red[threadIdx.x + s];
        __syncthreads();
    }
    float rs = rsqrtf(red[0] * (1.0f/(float)D_) + 1e-6f);
#pragma unroll
    for (int j = 0; j < 4; j++) {
        int d = threadIdx.x + j*256;
        Y[(size_t)row * D_ + d] = __float2half(vals[j] * rs * w[d]);
    }
}

// ---------------- mma helpers ----------------
__device__ __forceinline__ void mma16816(float* c, const uint32_t* a, const uint32_t* b)
{
    asm volatile(
        "mma.sync.aligned.m16n8k16.row.col.f32.f16.f16.f32 "
        "{%0,%1,%2,%3}, {%4,%5,%6,%7}, {%8,%9}, {%0,%1,%2,%3};\n"
        : "+f"(c[0]), "+f"(c[1]), "+f"(c[2]), "+f"(c[3])
        : "r"(a[0]), "r"(a[1]), "r"(a[2]), "r"(a[3]), "r"(b[0]), "r"(b[1]));
}
__device__ __forceinline__ void cp16(uint32_t dst, const void* src)
{
    asm volatile("cp.async.cg.shared.global [%0], [%1], 16;\n" :: "r"(dst), "l"(src));
}
__device__ __forceinline__ void ldm_x4(uint32_t& r0, uint32_t& r1, uint32_t& r2, uint32_t& r3,
                                       uint32_t addr)
{
    asm volatile("ldmatrix.sync.aligned.m8n8.x4.shared.b16 {%0,%1,%2,%3}, [%4];"
                 : "=r"(r0), "=r"(r1), "=r"(r2), "=r"(r3) : "r"(addr));
}
__device__ __forceinline__ uint32_t smem_u32(const void* p) {
    return (uint32_t)__cvta_generic_to_shared(p);
}

// ---------------- async HMMA GEMM (4 warps, 64-wide warp tiles) ----------------
// OP=0: f32 store.  OP=1: f32 accumulate.  OP=2: f16 store.
// OP=3: fused silu(gate)*up -> f16 [M, N/2] (weights interleaved gate/up).
#define BN 128
#define BKT 32
#define BSTG (BN*BKT*2)

template<int OP, int MT>
__global__ void __launch_bounds__(128, 2)
gemm_async(const __half* __restrict__ A, const __half* __restrict__ Wh,
           const float* __restrict__ Sc, void* __restrict__ Cv,
           int M, int N, int K)
{
    constexpr int BM   = MT * 32;
    constexpr int ASTG = BM * BKT * 2;
    __shared__ __align__(16) __half As[3][BM*BKT];
    __shared__ __align__(16) __half Bs[3][BN*BKT];

    const int tid  = threadIdx.x;
    const int lane = tid & 31;
    const int wid  = tid >> 5;            // 0..3
    const int warp_m = wid >> 1;          // 0..1
    const int warp_n = wid & 1;           // 0..1 (64 cols each)
    const int m0 = blockIdx.x * BM;
    const int n0 = blockIdx.y * BN;
    const int ngroups = K >> 7;
    const int gid = lane >> 2, tig = lane & 3;

    const uint32_t sa = smem_u32(&As[0][0]);
    const uint32_t sb = smem_u32(&Bs[0][0]);

    const int a_row  = lane & 15;
    const int a_sel  = lane >> 4;
    const int a_xor  = ((lane & 15) >> 1) & 3;
    const int b_roff = ((lane >> 4) << 3) + (lane & 7);
    const int b_sel  = (lane >> 3) & 1;
    const int b_xor  = (b_roff >> 1) & 3;

    float acc[MT][8][4] = {};
    float s_cur[8][2];
    float s_nxt[8][2];

    const int iters = K / BKT;

    auto issue = [&](int stage, int k0) {
        uint32_t ab = sa + stage * ASTG;
        uint32_t bb = sb + stage * BSTG;
#pragma unroll
        for (int j = 0; j < MT; j++) {
            int c = tid + j*128;
            int row = c >> 2, ch = c & 3;
            int pch = ch ^ ((row >> 1) & 3);
            cp16(ab + row*64 + pch*16, A  + (size_t)(m0+row)*K + k0 + ch*8);
        }
#pragma unroll
        for (int j = 0; j < 4; j++) {
            int c = tid + j*128;
            int row = c >> 2, ch = c & 3;
            int pch = ch ^ ((row >> 1) & 3);
            cp16(bb + row*64 + pch*16, Wh + (size_t)(n0+row)*K + k0 + ch*8);
        }
        asm volatile("cp.async.commit_group;\n");
    };

    issue(0, 0);
    issue(1, BKT);

    int stage = 0;
    for (int it = 0; it < iters; it++) {
        if (it + 1 < iters) asm volatile("cp.async.wait_group 1;\n");
        else                asm volatile("cp.async.wait_group 0;\n");
        __syncthreads();

        if ((it & 3) == 0) {
            int g = it >> 2;
#pragma unroll
            for (int nt = 0; nt < 8; nt++) {
                int nc = warp_n*64 + nt*8 + 2*tig;
                float ns0, ns1;
                if (g == 0) {
                    ns0 = Sc[(size_t)(n0 + nc)    *ngroups];
                    ns1 = Sc[(size_t)(n0 + nc + 1)*ngroups];
                } else {
                    ns0 = s_nxt[nt][0]; ns1 = s_nxt[nt][1];
                }
                if (it) {
                    float r0 = __fdividef(s_cur[nt][0], ns0);
                    float r1 = __fdividef(s_cur[nt][1], ns1);
#pragma unroll
                    for (int mt = 0; mt < MT; mt++) {
                        acc[mt][nt][0] *= r0; acc[mt][nt][1] *= r1;
                        acc[mt][nt][2] *= r0; acc[mt][nt][3] *= r1;
                    }
                }
                s_cur[nt][0] = ns0; s_cur[nt][1] = ns1;
            }
            if (g + 1 < ngroups) {
#pragma unroll
                for (int nt = 0; nt < 8; nt++) {
                    int nc = warp_n*64 + nt*8 + 2*tig;
                    s_nxt[nt][0] = Sc[(size_t)(n0 + nc)    *ngroups + g + 1];
                    s_nxt[nt][1] = Sc[(size_t)(n0 + nc + 1)*ngroups + g + 1];
                }
            }
        }

        const uint32_t ab = sa + stage * ASTG;
        const uint32_t bb = sb + stage * BSTG;
#pragma unroll
        for (int kk = 0; kk < 2; kk++) {
            uint32_t af[MT][4];
#pragma unroll
            for (int mt = 0; mt < MT; mt++) {
                int row = warp_m*(16*MT) + mt*16 + a_row;
                int pch = (kk*2 + a_sel) ^ a_xor;
                ldm_x4(af[mt][0], af[mt][1], af[mt][2], af[mt][3],
                       ab + row*64 + pch*16);
            }
            uint32_t bf[8][2];
#pragma unroll
            for (int p = 0; p < 4; p++) {
                int row = warp_n*64 + p*16 + b_roff;
                int pch = (kk*2 + b_sel) ^ b_xor;
                uint32_t r0, r1, r2, r3;
                ldm_x4(r0, r1, r2, r3, bb + row*64 + pch*16);
                bf[2*p  ][0] = r0; bf[2*p  ][1] = r1;
                bf[2*p+1][0] = r2; bf[2*p+1][1] = r3;
            }
#pragma unroll
            for (int mt = 0; mt < MT; mt++)
#pragma unroll
                for (int nt = 0; nt < 8; nt++)
                    mma16816(acc[mt][nt], af[mt], bf[nt]);
        }

        if (it + 2 < iters) issue((stage + 2 >= 3) ? stage - 1 : stage + 2, (it + 2) * BKT);
        stage = (stage + 1 == 3) ? 0 : stage + 1;
    }

    // ---- epilogue ----
#pragma unroll
    for (int mt = 0; mt < MT; mt++) {
        int r = m0 + warp_m*(16*MT) + mt*16 + gid;
#pragma unroll
        for (int nt = 0; nt < 8; nt++) {
            int c = n0 + warp_n*64 + nt*8 + 2*tig;
            float s0 = s_cur[nt][0], s1 = s_cur[nt][1];
            float v00 = acc[mt][nt][0]*s0, v01 = acc[mt][nt][1]*s1;
            float v10 = acc[mt][nt][2]*s0, v11 = acc[mt][nt][3]*s1;
            if (OP == 0 || OP == 1) {
                float* C = (float*)Cv;
                float* p0 = C + (size_t)r*N + c;
                float* p1 = C + (size_t)(r+8)*N + c;
                float2 v0 = make_float2(v00, v01);
                float2 v1 = make_float2(v10, v11);
                if (OP == 1) {
                    float2 o0 = *(float2*)p0, o1 = *(float2*)p1;
                    v0.x += o0.x; v0.y += o0.y; v1.x += o1.x; v1.y += o1.y;
                }
                *(float2*)p0 = v0;
                *(float2*)p1 = v1;
            } else if (OP == 2) {
                __half* C = (__half*)Cv;
                *(__half2*)(C + (size_t)r*N + c)     = __floats2half2_rn(v00, v01);
                *(__half2*)(C + (size_t)(r+8)*N + c) = __floats2half2_rn(v10, v11);
            } else {
                __half* C = (__half*)Cv;
                int oN = N >> 1, oc = c >> 1;
                float o0 = v00 / (1.f + __expf(-v00)) * v01;
                float o1 = v10 / (1.f + __expf(-v10)) * v11;
                C[(size_t)r*oN + oc]     = __float2half(o0);
                C[(size_t)(r+8)*oN + oc] = __float2half(o1);
            }
        }
    }
}

// ---------------- mma flash attention + per-head residual ----------------
// Vt uses a XOR-swizzled [64][64] layout: chunk' = chunk ^ (row&7) ^ ((row>>3)&7)
#define AQ 64
#define QKVS (3*D_)
__global__ void __launch_bounds__(128)
attn_mma(const __half* __restrict__ QKV, const __half* __restrict__ Hn,
         const float* __restrict__ alpha, __half* __restrict__ O, int layer)
{
    __shared__ __align__(16) __half Qs[AQ][72];
    __shared__ __align__(16) __half Ks[AQ][72];
    __shared__ __align__(16) __half Vt[AQ][64];   // swizzled [dh][key]

    const int tid = threadIdx.x, lane = tid & 31, wid = tid >> 5;
    const int qt = blockIdx.x, hh = blockIdx.y, b = blockIdx.z;
    const int q0 = qt * AQ;

    for (int t = tid; t < AQ*8; t += 128) {
        int r = t >> 3, c8 = t & 7;
        *(uint4*)&Qs[r][c8*8] =
            *(const uint4*)(QKV + ((size_t)(b*S_ + q0 + r))*QKVS + hh*DH_ + c8*8);
    }
    __syncthreads();

    uint32_t qf[4][4];
    {
        int rr = wid*16 + (lane & 15);
        int cc = ((lane >> 4) & 1) * 8;
#pragma unroll
        for (int ks = 0; ks < 4; ks++)
            ldm_x4(qf[ks][0], qf[ks][1], qf[ks][2], qf[ks][3],
                   smem_u32(&Qs[rr][ks*16 + cc]));
    }

    float o[8][4] = {};
    float m_lo = -1e30f, m_hi = -1e30f, l_lo = 0.f, l_hi = 0.f;
    const int qi_lo = q0 + wid*16 + (lane >> 2);
    const int qi_hi = qi_lo + 8;
    const int row_off = ((lane >> 4) << 3) + (lane & 7);
    const int col_sel = ((lane >> 3) & 1) * 8;

    for (int t0 = 0; t0 < q0 + AQ; t0 += AQ) {
        __syncthreads();
        for (int t = tid; t < AQ*8; t += 128) {
            int r = t >> 3, c8 = t & 7;
            const __half* base = QKV + ((size_t)(b*S_ + t0 + r))*QKVS + hh*DH_ + c8*8;
            *(uint4*)&Ks[r][c8*8] = *(const uint4*)(base + D_);
            uint4 raw = *(const uint4*)(base + 2*D_);
            const __half* hp = (const __half*)&raw;
            int rc = r >> 3, rw = r & 7;
#pragma unroll
            for (int d = 0; d < 8; d++) {
                int sc = rc ^ d ^ c8;
                Vt[c8*8 + d][sc*8 + rw] = hp[d];
            }
        }
        __syncthreads();

        float sacc[8][4] = {};
#pragma unroll
        for (int ks = 0; ks < 4; ks++) {
#pragma unroll
            for (int jp = 0; jp < 4; jp++) {
                uint32_t r0, r1, r2, r3;
                ldm_x4(r0, r1, r2, r3, smem_u32(&Ks[jp*16 + row_off][ks*16 + col_sel]));
                uint32_t bA[2] = {r0, r1};
                uint32_t bB[2] = {r2, r3};
                mma16816(sacc[2*jp  ], qf[ks], bA);
                mma16816(sacc[2*jp+1], qf[ks], bB);
            }
        }

        float mx_lo = -1e30f, mx_hi = -1e30f;
#pragma unroll
        for (int j = 0; j < 8; j++) {
            int kb = t0 + j*8 + 2*(lane & 3);
            sacc[j][0] = (kb     <= qi_lo) ? sacc[j][0]*0.125f : -1e30f;
            sacc[j][1] = (kb + 1 <= qi_lo) ? sacc[j][1]*0.125f : -1e30f;
            sacc[j][2] = (kb     <= qi_hi) ? sacc[j][2]*0.125f : -1e30f;
            sacc[j][3] = (kb + 1 <= qi_hi) ? sacc[j][3]*0.125f : -1e30f;
            mx_lo = fmaxf(mx_lo, fmaxf(sacc[j][0], sacc[j][1]));
            mx_hi = fmaxf(mx_hi, fmaxf(sacc[j][2], sacc[j][3]));
        }
        mx_lo = fmaxf(mx_lo, __shfl_xor_sync(0xffffffffu, mx_lo, 1));
        mx_lo = fmaxf(mx_lo, __shfl_xor_sync(0xffffffffu, mx_lo, 2));
        mx_hi = fmaxf(mx_hi, __shfl_xor_sync(0xffffffffu, mx_hi, 1));
        mx_hi = fmaxf(mx_hi, __shfl_xor_sync(0xffffffffu, mx_hi, 2));

        float mn_lo = fmaxf(m_lo, mx_lo), mn_hi = fmaxf(m_hi, mx_hi);
        float c_lo = __expf(m_lo - mn_lo), c_hi = __expf(m_hi - mn_hi);
        m_lo = mn_lo; m_hi = mn_hi;
        l_lo *= c_lo; l_hi *= c_hi;
#pragma unroll
        for (int j = 0; j < 8; j++) {
            o[j][0] *= c_lo; o[j][1] *= c_lo;
            o[j][2] *= c_hi; o[j][3] *= c_hi;
        }

        uint32_t pa[8], pb[8];
        float ps_lo = 0.f, ps_hi = 0.f;
#pragma unroll
        for (int j = 0; j < 8; j++) {
            float e0 = __expf(sacc[j][0] - mn_lo);
            float e1 = __expf(sacc[j][1] - mn_lo);
            float e2 = __expf(sacc[j][2] - mn_hi);
            float e3 = __expf(sacc[j][3] - mn_hi);
            ps_lo += e0 + e1; ps_hi += e2 + e3;
            __half2 hl = __floats2half2_rn(e0, e1);
            __half2 hb = __floats2half2_rn(e2, e3);
            pa[j] = *(uint32_t*)&hl;
            pb[j] = *(uint32_t*)&hb;
        }
        ps_lo += __shfl_xor_sync(0xffffffffu, ps_lo, 1);
        ps_lo += __shfl_xor_sync(0xffffffffu, ps_lo, 2);
        ps_hi += __shfl_xor_sync(0xffffffffu, ps_hi, 1);
        ps_hi += __shfl_xor_sync(0xffffffffu, ps_hi, 2);
        l_lo += ps_lo; l_hi += ps_hi;

#pragma unroll
        for (int kk = 0; kk < 4; kk++) {
            uint32_t af[4] = {pa[2*kk], pb[2*kk], pa[2*kk+1], pb[2*kk+1]};
#pragma unroll
            for (int dp = 0; dp < 4; dp++) {
                int row = dp*16 + row_off;
                int chunk = kk*2 + (col_sel >> 3);
                int sc = chunk ^ (row & 7) ^ ((row >> 3) & 7);
                uint32_t r0, r1, r2, r3;
                ldm_x4(r0, r1, r2, r3, smem_u32(&Vt[row][sc*8]));
                uint32_t bA[2] = {r0, r1};
                uint32_t bB[2] = {r2, r3};
                mma16816(o[2*dp  ], af, bA);
                mma16816(o[2*dp+1], af, bB);
            }
        }
    }

    float i_lo = 1.f / l_lo, i_hi = 1.f / l_hi;
    float a = alpha[layer*H_ + hh];
    size_t tok_lo = (size_t)(b*S_ + qi_lo);
#pragma unroll
    for (int j = 0; j < 8; j++) {
        int col = hh*DH_ + j*8 + 2*(lane & 3);
        float2 fh_lo = __half22float2(*(const __half2*)(Hn + tok_lo*D_ + col));
        float2 fh_hi = __half22float2(*(const __half2*)(Hn + (tok_lo+8)*D_ + col));
        __half2 o_lo = __floats2half2_rn(o[j][0]*i_lo + a*fh_lo.x,
                                         o[j][1]*i_lo + a*fh_lo.y);
        __half2 o_hi = __floats2half2_rn(o[j][2]*i_hi + a*fh_hi.x,
                                         o[j][3]*i_hi + a*fh_hi.y);
        *(__half2*)(O + tok_lo*D_ + col)     = o_lo;
        *(__half2*)(O + (tok_lo+8)*D_ + col) = o_hi;
    }
}

// ---------------- launch ----------------
extern "C" void kernel_launch(void* const* d_in, const int* in_sizes, int n_in,
                              void* d_out, int out_size)
{
    const int*   ids    = (const int*)  d_in[0];
    const void*  emb_t  = d_in[1];
    const float* emb_s  = (const float*)d_in[2];
    const void*  qt_    = d_in[3];
    const float* qs_    = (const float*)d_in[4];
    const void*  kt_    = d_in[5];
    const float* ks_    = (const float*)d_in[6];
    const void*  vt_    = d_in[7];
    const float* vs_    = (const float*)d_in[8];
    const void*  ot_    = d_in[9];
    const float* os_    = (const float*)d_in[10];
    const void*  gatet  = d_in[11];
    const float* gates  = (const float*)d_in[12];
    const void*  upt    = d_in[13];
    const float* ups    = (const float*)d_in[14];
    const void*  downt  = d_in[15];
    const float* downs  = (const float*)d_in[16];
    const float* wa     = (const float*)d_in[17];
    const float* wm     = (const float*)d_in[18];
    const float* alpha  = (const float*)d_in[19];
    const float* wf     = (const float*)d_in[20];
    const void*  headt  = d_in[21];
    const float* heads  = (const float*)d_in[22];
    float* out = (float*)d_out;

    float *x, *scqkv, *scgu;
    __half *qkv, *hh, *oh, *gh, *wh;
    cudaGetSymbolAddress((void**)&x,    g_x);
    cudaGetSymbolAddress((void**)&qkv,  g_qkv);
    cudaGetSymbolAddress((void**)&hh,   g_hh);
    cudaGetSymbolAddress((void**)&oh,   g_oh);
    cudaGetSymbolAddress((void**)&gh,   g_gh);
    cudaGetSymbolAddress((void**)&wh,   g_wh);
    cudaGetSymbolAddress((void**)&scqkv,g_scqkv);
    cudaGetSymbolAddress((void**)&scgu, g_scgu);

    // side stream: weight conversion overlapped with compute (round-14 layout)
    static cudaStream_t s2 = nullptr;
    static cudaEvent_t evFork = nullptr, evL[2] = {nullptr, nullptr}, evH = nullptr;
    if (!s2) {
        cudaStreamCreate(&s2);
        cudaEventCreateWithFlags(&evFork, cudaEventDisableTiming);
        cudaEventCreateWithFlags(&evL[0], cudaEventDisableTiming);
        cudaEventCreateWithFlags(&evL[1], cudaEventDisableTiming);
        cudaEventCreateWithFlags(&evH,    cudaEventDisableTiming);
    }

    const size_t wDD = (size_t)D_*D_;          // 1M
    const size_t wFD = (size_t)DFF_*D_;        // 4M
    const size_t sDD = wDD/GS_;                // 8192
    const size_t sFD = wFD/GS_;                // 32768

    detect_fmt_kernel<<<1, 1>>>(emb_t);
    cudaEventRecord(evFork, 0);
    cudaStreamWaitEvent(s2, evFork, 0);

    // per-layer weight conversion + head, all on s2 with per-stage events
    for (int l = 0; l < L_; l++) {
        ConvSegs P;
        int c = 0, seg = 0;
        auto add = [&](const void* src, size_t soff, size_t doff, int nelems, int mode) {
            P.src[seg] = src; P.srcOff[seg] = soff; P.dstOff[seg] = doff;
            P.mode[seg] = mode; c += nelems / 16; P.chunkEnd[seg] = c; seg++;
        };
        add(qt_,   l*wDD, OFF_QKV + l*3*wDD,         (int)wDD, 0);
        add(kt_,   l*wDD, OFF_QKV + l*3*wDD + wDD,   (int)wDD, 0);
        add(vt_,   l*wDD, OFF_QKV + l*3*wDD + 2*wDD, (int)wDD, 0);
        add(ot_,   l*wDD, OFF_O   + l*wDD,           (int)wDD, 0);
        add(gatet, l*wFD, OFF_GU  + l*2*wFD,         (int)wFD, 1);
        add(upt,   l*wFD, OFF_GU  + l*2*wFD,         (int)wFD, 2);
        add(downt, l*wFD, OFF_DN  + l*wFD,           (int)wFD, 0);
        P.total = c;
        convert_all<<<(P.total + 255)/256, 256, 0, s2>>>(P, wh);
        cudaEventRecord(evL[l], s2);
    }
    {
        ConvSegs PH;
        int c = (int)((V_*(size_t)D_)/16);
        for (int s = 0; s < NSEG; s++) PH.chunkEnd[s] = c;
        PH.src[0] = headt; PH.srcOff[0] = 0; PH.dstOff[0] = OFF_HD; PH.mode[0] = 0;
        PH.total = c;
        convert_all<<<(PH.total + 255)/256, 256, 0, s2>>>(PH, wh);
        cudaEventRecord(evH, s2);
    }

    pack_scales<<<(180224 + 255)/256, 256>>>(qs_, ks_, vs_, gates, ups, scqkv, scgu);
    embed_kernel<<<NT_, 256>>>(ids, emb_t, emb_s, x);

    dim3 g_qkvp(NT_/128, 3*D_/BN);   // 16 x 24
    dim3 g_op  (NT_/64,  D_/BN);     // 32 x 8  (BM=64)
    dim3 g_gup (NT_/128, 2*DFF_/BN); // 16 x 64
    dim3 g_hd  (NT_/128, V_/BN);     // 16 x 250

    for (int l = 0; l < L_; l++) {
        rmsnorm_kernel<<<NT_, 256>>>(x, wa + (size_t)l*D_, hh);
        cudaStreamWaitEvent(0, evL[l], 0);
        gemm_async<2,4><<<g_qkvp, 128>>>(hh, wh + OFF_QKV + l*3*wDD, scqkv + l*3*sDD,
                                         qkv, NT_, 3*D_, D_);
        attn_mma<<<dim3(S_/AQ, H_, B_), 128>>>(qkv, hh, alpha, oh, l);
        gemm_async<1,2><<<g_op, 128>>>(oh, wh + OFF_O + l*wDD, os_ + l*sDD,
                                       x, NT_, D_, D_);

        rmsnorm_kernel<<<NT_, 256>>>(x, wm + (size_t)l*D_, hh);
        gemm_async<3,4><<<g_gup, 128>>>(hh, wh + OFF_GU + l*2*wFD, scgu + l*2*sFD,
                                        gh, NT_, 2*DFF_, D_);
        gemm_async<1,2><<<g_op, 128>>>(gh, wh + OFF_DN + l*wFD, downs + l*sFD,
                                       x, NT_, D_, DFF_);
    }
    rmsnorm_kernel<<<NT_, 256>>>(x, wf, hh);

    cudaStreamWaitEvent(0, evH, 0);
    gemm_async<0,4><<<g_hd, 128>>>(hh, wh + OFF_HD, heads, out, NT_, V_, D_);
}